// round 4
// baseline (speedup 1.0000x reference)
#include <cuda_runtime.h>

#define TT   65536
#define NB   (TT/2)
#define SD   100
#define HID  8
#define NOBS 12
#define DTC  0.01f

__device__ __forceinline__ unsigned long long pack2(float lo, float hi) {
    unsigned long long r;
    asm("mov.b64 %0, {%1, %2};" : "=l"(r) : "f"(lo), "f"(hi));
    return r;
}
__device__ __forceinline__ void unpack2(unsigned long long v, float& lo, float& hi) {
    asm("mov.b64 {%0, %1}, %2;" : "=f"(lo), "=f"(hi) : "l"(v));
}
__device__ __forceinline__ void fma2(unsigned long long& acc, unsigned long long a, unsigned long long b) {
    asm("fma.rn.f32x2 %0, %1, %2, %0;" : "+l"(acc) : "l"(a), "l"(b));
}
__device__ __forceinline__ void add2(unsigned long long& acc, unsigned long long b) {
    asm("add.rn.f32x2 %0, %0, %1;" : "+l"(acc) : "l"(b));
}
__device__ __forceinline__ float tanh_hw(float x) {
    float r;
    asm("tanh.approx.f32 %0, %1;" : "=f"(r) : "f"(x));
    return r;
}

// ---------------- device scratch (static, allowed) ----------------
__device__ float g_At[SD * SD];           // A transposed (for coalesced column access)
__device__ float g_A2[SD * SD];           // A^2
__device__ float g_dtA2W2[SD * HID];      // A^2 @ (dt W2)
__device__ float g_dtAW2[SD * HID];       // A @ (dt W2)
__device__ float g_W1A[HID * SD];         // W1 @ A
__device__ float g_dtW1AW2[HID * HID];    // (W1 A) @ (dt W2)
__device__ float g_dtW1W2[HID * HID];     // W1 @ (dt W2)
__device__ float g_ABw[SD * 2];           // A @ Bw
__device__ float g_cP[SD];                // dt (A + I) b2
__device__ float g_W1Bw[HID * 2];         // W1 @ Bw
__device__ float g_cQ[HID];               // dt W1 b2
__device__ float g_P[(size_t)NB * SD];    // per-block input composite for g
__device__ float g_Q[(size_t)NB * HID];   // per-block input composite for h2
__device__ float g_h[((size_t)TT + 1) * HID]; // all hidden states h_1..h_T

// ============================================================================
// 1) setup: composite matrices (one block, one-time ~25us)
// ============================================================================
__global__ void __launch_bounds__(128, 1) setup_kernel(
    const float* __restrict__ A, const float* __restrict__ Bw,
    const float* __restrict__ W1, const float* __restrict__ W2,
    const float* __restrict__ b2)
{
    __shared__ float As[SD * SD];
    __shared__ float W2d[SD * HID];
    __shared__ float W1s[HID * SD];
    int tid = threadIdx.x;
    for (int i = tid; i < SD * SD; i += 128) As[i] = A[i];
    for (int i = tid; i < SD * HID; i += 128) W2d[i] = DTC * W2[i];
    for (int i = tid; i < HID * SD; i += 128) W1s[i] = W1[i];
    __syncthreads();
    for (int i = tid; i < SD * SD; i += 128) {
        int r = i / SD, c = i % SD;
        g_At[c * SD + r] = As[i];
    }
    if (tid < SD) {
        int i = tid;
        float acc[SD];
#pragma unroll
        for (int j = 0; j < SD; j++) acc[j] = 0.f;
        for (int j = 0; j < SD; j++) {
            float a = As[i * SD + j];
#pragma unroll
            for (int jj = 0; jj < SD; jj++) acc[jj] += a * As[j * SD + jj];
        }
        for (int jj = 0; jj < SD; jj++) g_A2[i * SD + jj] = acc[jj];
        for (int z = 0; z < HID; z++) {
            float s = 0.f, s2 = 0.f;
            for (int jj = 0; jj < SD; jj++) {
                s  += acc[jj] * W2d[jj * HID + z];
                s2 += As[i * SD + jj] * W2d[jj * HID + z];
            }
            g_dtA2W2[i * HID + z] = s;
            g_dtAW2[i * HID + z] = s2;
        }
        float s0 = 0.f, s1 = 0.f, sb = 0.f;
        for (int j = 0; j < SD; j++) {
            s0 += As[i * SD + j] * Bw[j * 2];
            s1 += As[i * SD + j] * Bw[j * 2 + 1];
            sb += As[i * SD + j] * b2[j];
        }
        g_ABw[i * 2] = s0; g_ABw[i * 2 + 1] = s1;
        g_cP[i] = DTC * (sb + b2[i]);
    } else if (tid >= 104 && tid < 112) {
        int z = tid - 104;
        float acc[SD];
#pragma unroll
        for (int j = 0; j < SD; j++) acc[j] = 0.f;
        for (int j = 0; j < SD; j++) {
            float a = W1s[z * SD + j];
#pragma unroll
            for (int jj = 0; jj < SD; jj++) acc[jj] += a * As[j * SD + jj];
        }
        for (int jj = 0; jj < SD; jj++) g_W1A[z * SD + jj] = acc[jj];
        for (int zz = 0; zz < HID; zz++) {
            float s = 0.f, s2 = 0.f;
            for (int jj = 0; jj < SD; jj++) {
                s  += acc[jj] * W2d[jj * HID + zz];
                s2 += W1s[z * SD + jj] * W2d[jj * HID + zz];
            }
            g_dtW1AW2[z * HID + zz] = s;
            g_dtW1W2[z * HID + zz] = s2;
        }
        float s0 = 0.f, s1 = 0.f, sb = 0.f;
        for (int j = 0; j < SD; j++) {
            s0 += W1s[z * SD + j] * Bw[j * 2];
            s1 += W1s[z * SD + j] * Bw[j * 2 + 1];
            sb += W1s[z * SD + j] * b2[j];
        }
        g_W1Bw[z * 2] = s0; g_W1Bw[z * 2 + 1] = s1;
        g_cQ[z] = DTC * sb;
    }
}

// ============================================================================
// 2) precompute P_b = A in_{2b} + in_{2b+1},  Q_b = W1 in_{2b} (h-projection)
//    in_t = Bw w_t + u_t + dt b2.  Fully parallel over 32768 blocks.
// ============================================================================
__global__ void precomp_kernel(const float* __restrict__ w,
                               const float* __restrict__ u,
                               const float* __restrict__ Bw,
                               const float* __restrict__ W1)
{
    __shared__ float us[SD];
    int b = blockIdx.x;
    int k = 2 * b;
    int tid = threadIdx.x;
    if (tid < SD) us[tid] = u[(size_t)k * SD + tid];
    __syncthreads();
    float wk0 = w[2 * k], wk1 = w[2 * k + 1];
    float wn0 = w[2 * k + 2], wn1 = w[2 * k + 3];
    if (tid < SD) {
        int i = tid;
        float acc = u[(size_t)(k + 1) * SD + i] + g_cP[i]
                  + g_ABw[i * 2] * wk0 + g_ABw[i * 2 + 1] * wk1
                  + Bw[i * 2] * wn0 + Bw[i * 2 + 1] * wn1;
        for (int j = 0; j < SD; j++) acc += g_At[j * SD + i] * us[j];
        g_P[(size_t)b * SD + i] = acc;
    } else if (tid >= 104 && tid < 112) {
        int z = tid - 104;
        float acc = g_cQ[z] + g_W1Bw[z * 2] * wk0 + g_W1Bw[z * 2 + 1] * wk1;
        for (int j = 0; j < SD; j++) acc += W1[z * SD + j] * us[j];
        g_Q[(size_t)b * HID + z] = acc;
    }
}

// ============================================================================
// 3) serial rollout over 32768 two-step blocks. 1 block, 128 threads.
//    s_k = [g_k (100) | h_k (8)].  Per block: one 108-dot per lane + tiny phase2.
//    Stores g_{k+2} into outc row (k+1) [raw g; fixed up by postEven],
//    h_{k+1}, h_{k+2} into g_h.
// ============================================================================
__global__ void __launch_bounds__(128, 1) serial_kernel(
    const float* __restrict__ c0,
    const float* __restrict__ W1,
    const float* __restrict__ b1,
    float* __restrict__ outc)
{
    __shared__ __align__(16) float sbuf[2][112];
    __shared__ __align__(16) float sh1[8];

    const int tid = threadIdx.x;
    const bool isG  = (tid < SD);
    const bool isM0 = (tid >= 104 && tid < 112);
    const bool isM1 = (tid >= 112 && tid < 120);
    const int z0 = tid - 104;
    const int z1 = tid - 112;

    if (tid < 112) { sbuf[0][tid] = (tid < SD) ? c0[tid] : 0.f; sbuf[1][tid] = 0.f; }

    unsigned long long rva[54];
#pragma unroll
    for (int q = 0; q < 54; q++) rva[q] = 0ull;
    unsigned long long w4[4] = {0ull, 0ull, 0ull, 0ull};
    float bias = 0.f;

    if (isG) {
        const float* R = g_A2 + tid * SD;
#pragma unroll
        for (int q = 0; q < 50; q++) rva[q] = pack2(R[2 * q], R[2 * q + 1]);
        const float* R2 = g_dtA2W2 + tid * HID;
#pragma unroll
        for (int q = 0; q < 4; q++) rva[50 + q] = pack2(R2[2 * q], R2[2 * q + 1]);
        const float* R3 = g_dtAW2 + tid * HID;
#pragma unroll
        for (int q = 0; q < 4; q++) w4[q] = pack2(R3[2 * q], R3[2 * q + 1]);
    } else if (isM0) {
        const float* R = W1 + z0 * SD;
#pragma unroll
        for (int q = 0; q < 50; q++) rva[q] = pack2(R[2 * q], R[2 * q + 1]);
        const float* R2 = g_dtW1W2 + z0 * HID;
#pragma unroll
        for (int q = 0; q < 4; q++) rva[50 + q] = pack2(R2[2 * q], R2[2 * q + 1]);
        bias = b1[z0];
    } else if (isM1) {
        const float* R = g_W1A + z1 * SD;
#pragma unroll
        for (int q = 0; q < 50; q++) rva[q] = pack2(R[2 * q], R[2 * q + 1]);
        const float* R2 = g_dtW1AW2 + z1 * HID;
#pragma unroll
        for (int q = 0; q < 4; q++) rva[50 + q] = pack2(R2[2 * q], R2[2 * q + 1]);
        const float* R3 = g_dtW1W2 + z1 * HID;
#pragma unroll
        for (int q = 0; q < 4; q++) w4[q] = pack2(R3[2 * q], R3[2 * q + 1]);
        bias = b1[z1];
    }
    __syncthreads();

    // prefetch P/Q, depth 2 blocks
    float p_c = 0.f, p_n = 0.f;
    if (isG)       { p_c = g_P[tid];       p_n = g_P[SD + tid]; }
    else if (isM1) { p_c = g_Q[z1];        p_n = g_Q[HID + z1]; }

    int p = 0;
    for (int b = 0; b < NB; b++) {
        const int bn = (b + 2 < NB) ? (b + 2) : (NB - 1);
        float p_n2 = 0.f;
        if (isG)       p_n2 = __ldcg(&g_P[(size_t)bn * SD + tid]);
        else if (isM1) p_n2 = __ldcg(&g_Q[(size_t)bn * HID + z1]);

        // ---- phase 1: one 108-dot against s_k (all lane classes concurrently)
        unsigned long long a0 = 0ull, a1 = 0ull, a2 = 0ull, a3 = 0ull;
        const ulonglong2* sp = reinterpret_cast<const ulonglong2*>(sbuf[p]);
#pragma unroll
        for (int q = 0; q < 27; q++) {
            ulonglong2 gg = sp[q];
            if (q & 1) { fma2(a2, rva[2 * q], gg.x); fma2(a3, rva[2 * q + 1], gg.y); }
            else       { fma2(a0, rva[2 * q], gg.x); fma2(a1, rva[2 * q + 1], gg.y); }
        }
        add2(a0, a1); add2(a2, a3); add2(a0, a2);
        float lo, hi; unpack2(a0, lo, hi);
        float dot = lo + hi;

        float h1r = 0.f;
        if (isM0) { h1r = tanh_hw(dot + bias); sh1[z0] = h1r; }
        __syncthreads();   // bar1: h_{k+1} visible

        // ---- phase 2: apply h_{k+1} coupling
        const ulonglong2* hp = reinterpret_cast<const ulonglong2*>(sh1);
        ulonglong2 Ha = hp[0], Hb = hp[1];
        if (isG) {
            unsigned long long c4 = 0ull;
            fma2(c4, w4[0], Ha.x); fma2(c4, w4[1], Ha.y);
            fma2(c4, w4[2], Hb.x); fma2(c4, w4[3], Hb.y);
            float l2, h2; unpack2(c4, l2, h2);
            float gn = dot + p_c + l2 + h2;
            sbuf[p ^ 1][tid] = gn;
            outc[(size_t)(2 * b + 1) * SD + tid] = gn;     // raw g_{k+2}
        } else if (isM1) {
            unsigned long long c4 = 0ull;
            fma2(c4, w4[0], Ha.x); fma2(c4, w4[1], Ha.y);
            fma2(c4, w4[2], Hb.x); fma2(c4, w4[3], Hb.y);
            float l2, h2; unpack2(c4, l2, h2);
            float hn = tanh_hw(dot + bias + p_c + l2 + h2);
            sbuf[p ^ 1][SD + z1] = hn;
            g_h[(size_t)(2 * b + 2) * HID + z1] = hn;
        } else if (isM0) {
            g_h[(size_t)(2 * b + 1) * HID + z0] = h1r;
        }

        p_c = p_n; p_n = p_n2;
        __syncthreads();   // bar2
        p ^= 1;
    }
}

// ============================================================================
// 4) postEven: even t (2..T): c_t = g_t + dt W2 h_t (in place, odd outc rows) + y
// ============================================================================
__global__ void postEven_kernel(const float* __restrict__ W2,
                                const int* __restrict__ obs,
                                float* __restrict__ outc,
                                float* __restrict__ outy)
{
    __shared__ float cs[SD];
    __shared__ float hh[HID];
    int t = 2 * blockIdx.x + 2;
    size_t r = (size_t)(t - 1);
    int tid = threadIdx.x;
    if (tid < HID) hh[tid] = g_h[(size_t)t * HID + tid];
    __syncthreads();
    if (tid < SD) {
        float g = outc[r * SD + tid];
        float s = 0.f;
#pragma unroll
        for (int z = 0; z < HID; z++) s += W2[tid * HID + z] * hh[z];
        float c = g + DTC * s;
        cs[tid] = c;
        outc[r * SD + tid] = c;
    }
    __syncthreads();
    if (tid < NOBS) outy[r * NOBS + tid] = cs[obs[tid]];
}

// ============================================================================
// 5) postOdd: odd t (1..T-1): c_t = A c_{t-1} + in_{t-1} + dt W2 h_t  + y
//    (c_{t-1} even: already finalized by postEven, or c0 for t=1)
// ============================================================================
__global__ void postOdd_kernel(const float* __restrict__ c0,
                               const float* __restrict__ w,
                               const float* __restrict__ u,
                               const float* __restrict__ Bw,
                               const float* __restrict__ W2,
                               const float* __restrict__ b2,
                               const int* __restrict__ obs,
                               float* __restrict__ outc,
                               float* __restrict__ outy)
{
    __shared__ float cp[SD];
    __shared__ float hh[HID];
    __shared__ float cs[SD];
    int b = blockIdx.x;
    int t = 2 * b + 1;
    size_t r = (size_t)(t - 1);
    int tid = threadIdx.x;
    if (tid < SD) cp[tid] = (b == 0) ? c0[tid] : outc[(r - 1) * SD + tid];
    if (tid < HID) hh[tid] = g_h[(size_t)t * HID + tid];
    __syncthreads();
    if (tid < SD) {
        int i = tid;
        float s = 0.f;
#pragma unroll
        for (int z = 0; z < HID; z++) s += W2[i * HID + z] * hh[z];
        float acc = u[(size_t)(t - 1) * SD + i] + DTC * (b2[i] + s)
                  + Bw[i * 2] * w[(t - 1) * 2] + Bw[i * 2 + 1] * w[(t - 1) * 2 + 1];
        for (int j = 0; j < SD; j++) acc += g_At[j * SD + i] * cp[j];
        cs[i] = acc;
        outc[r * SD + i] = acc;
    }
    __syncthreads();
    if (tid < NOBS) outy[r * NOBS + tid] = cs[obs[tid]];
}

extern "C" void kernel_launch(void* const* d_in, const int* in_sizes, int n_in,
                              void* d_out, int out_size) {
    const float* c0  = (const float*)d_in[0];
    const float* w   = (const float*)d_in[1];
    const float* u   = (const float*)d_in[2];
    const float* A   = (const float*)d_in[3];
    const float* Bw  = (const float*)d_in[4];
    const float* W1  = (const float*)d_in[5];
    const float* b1  = (const float*)d_in[6];
    const float* W2  = (const float*)d_in[7];
    const float* b2  = (const float*)d_in[8];
    const int*   ob  = (const int*)d_in[9];

    float* outc = (float*)d_out;                      // (T, 100)
    float* outy = (float*)d_out + (size_t)TT * SD;    // (T, 12)

    setup_kernel<<<1, 128>>>(A, Bw, W1, W2, b2);
    precomp_kernel<<<NB, 128>>>(w, u, Bw, W1);
    serial_kernel<<<1, 128>>>(c0, W1, b1, outc);
    postEven_kernel<<<NB, 128>>>(W2, ob, outc, outy);
    postOdd_kernel<<<NB, 128>>>(c0, w, u, Bw, W2, b2, ob, outc, outy);
}

// round 5
// speedup vs baseline: 1.0104x; 1.0104x over previous
#include <cuda_runtime.h>

#define TT   65536
#define NB   (TT/2)
#define SD   100
#define HID  8
#define NOBS 12
#define DTC  0.01f

__device__ __forceinline__ unsigned long long pack2(float lo, float hi) {
    unsigned long long r;
    asm("mov.b64 %0, {%1, %2};" : "=l"(r) : "f"(lo), "f"(hi));
    return r;
}
__device__ __forceinline__ void unpack2(unsigned long long v, float& lo, float& hi) {
    asm("mov.b64 {%0, %1}, %2;" : "=f"(lo), "=f"(hi) : "l"(v));
}
__device__ __forceinline__ void fma2(unsigned long long& acc, unsigned long long a, unsigned long long b) {
    asm("fma.rn.f32x2 %0, %1, %2, %0;" : "+l"(acc) : "l"(a), "l"(b));
}
__device__ __forceinline__ void add2(unsigned long long& acc, unsigned long long b) {
    asm("add.rn.f32x2 %0, %0, %1;" : "+l"(acc) : "l"(b));
}
__device__ __forceinline__ float tanh_hw(float x) {
    float r;
    asm("tanh.approx.f32 %0, %1;" : "=f"(r) : "f"(x));
    return r;
}

// ---------------- device scratch (static, allowed) ----------------
__device__ float g_At[SD * SD];           // A transposed (for coalesced column access)
__device__ float g_A2[SD * SD];           // A^2
__device__ float g_dtA2W2[SD * HID];      // A^2 @ (dt W2)
__device__ float g_dtAW2[SD * HID];       // A @ (dt W2)
__device__ float g_W1A[HID * SD];         // W1 @ A
__device__ float g_dtW1AW2[HID * HID];    // (W1 A) @ (dt W2)
__device__ float g_dtW1W2[HID * HID];     // W1 @ (dt W2)
__device__ float g_ABw[SD * 2];           // A @ Bw
__device__ float g_cP[SD];                // dt (A + I) b2
__device__ float g_W1Bw[HID * 2];         // W1 @ Bw
__device__ float g_cQ[HID];               // dt W1 b2
__device__ float g_P[(size_t)NB * SD];    // per-block input composite for g
__device__ float g_Q[(size_t)NB * HID];   // per-block input composite for h2
__device__ float g_h[((size_t)TT + 1) * HID]; // all hidden states h_1..h_T

// ============================================================================
// 1) setup: composite matrices (one block, one-time ~25us)
// ============================================================================
__global__ void __launch_bounds__(128, 1) setup_kernel(
    const float* __restrict__ A, const float* __restrict__ Bw,
    const float* __restrict__ W1, const float* __restrict__ W2,
    const float* __restrict__ b2)
{
    __shared__ float As[SD * SD];
    __shared__ float W2d[SD * HID];
    __shared__ float W1s[HID * SD];
    int tid = threadIdx.x;
    for (int i = tid; i < SD * SD; i += 128) As[i] = A[i];
    for (int i = tid; i < SD * HID; i += 128) W2d[i] = DTC * W2[i];
    for (int i = tid; i < HID * SD; i += 128) W1s[i] = W1[i];
    __syncthreads();
    for (int i = tid; i < SD * SD; i += 128) {
        int r = i / SD, c = i % SD;
        g_At[c * SD + r] = As[i];
    }
    if (tid < SD) {
        int i = tid;
        float acc[SD];
#pragma unroll
        for (int j = 0; j < SD; j++) acc[j] = 0.f;
        for (int j = 0; j < SD; j++) {
            float a = As[i * SD + j];
#pragma unroll
            for (int jj = 0; jj < SD; jj++) acc[jj] += a * As[j * SD + jj];
        }
        for (int jj = 0; jj < SD; jj++) g_A2[i * SD + jj] = acc[jj];
        for (int z = 0; z < HID; z++) {
            float s = 0.f, s2 = 0.f;
            for (int jj = 0; jj < SD; jj++) {
                s  += acc[jj] * W2d[jj * HID + z];
                s2 += As[i * SD + jj] * W2d[jj * HID + z];
            }
            g_dtA2W2[i * HID + z] = s;
            g_dtAW2[i * HID + z] = s2;
        }
        float s0 = 0.f, s1 = 0.f, sb = 0.f;
        for (int j = 0; j < SD; j++) {
            s0 += As[i * SD + j] * Bw[j * 2];
            s1 += As[i * SD + j] * Bw[j * 2 + 1];
            sb += As[i * SD + j] * b2[j];
        }
        g_ABw[i * 2] = s0; g_ABw[i * 2 + 1] = s1;
        g_cP[i] = DTC * (sb + b2[i]);
    } else if (tid >= 104 && tid < 112) {
        int z = tid - 104;
        float acc[SD];
#pragma unroll
        for (int j = 0; j < SD; j++) acc[j] = 0.f;
        for (int j = 0; j < SD; j++) {
            float a = W1s[z * SD + j];
#pragma unroll
            for (int jj = 0; jj < SD; jj++) acc[jj] += a * As[j * SD + jj];
        }
        for (int jj = 0; jj < SD; jj++) g_W1A[z * SD + jj] = acc[jj];
        for (int zz = 0; zz < HID; zz++) {
            float s = 0.f, s2 = 0.f;
            for (int jj = 0; jj < SD; jj++) {
                s  += acc[jj] * W2d[jj * HID + zz];
                s2 += W1s[z * SD + jj] * W2d[jj * HID + zz];
            }
            g_dtW1AW2[z * HID + zz] = s;
            g_dtW1W2[z * HID + zz] = s2;
        }
        float s0 = 0.f, s1 = 0.f, sb = 0.f;
        for (int j = 0; j < SD; j++) {
            s0 += W1s[z * SD + j] * Bw[j * 2];
            s1 += W1s[z * SD + j] * Bw[j * 2 + 1];
            sb += W1s[z * SD + j] * b2[j];
        }
        g_W1Bw[z * 2] = s0; g_W1Bw[z * 2 + 1] = s1;
        g_cQ[z] = DTC * sb;
    }
}

// ============================================================================
// 2) precompute P_b = A in_{2b} + in_{2b+1},  Q_b = W1 in_{2b} (h-projection)
//    in_t = Bw w_t + u_t + dt b2.  Fully parallel over 32768 blocks.
// ============================================================================
__global__ void precomp_kernel(const float* __restrict__ w,
                               const float* __restrict__ u,
                               const float* __restrict__ Bw,
                               const float* __restrict__ W1)
{
    __shared__ float us[SD];
    int b = blockIdx.x;
    int k = 2 * b;
    int tid = threadIdx.x;
    if (tid < SD) us[tid] = u[(size_t)k * SD + tid];
    __syncthreads();
    float wk0 = w[2 * k], wk1 = w[2 * k + 1];
    float wn0 = w[2 * k + 2], wn1 = w[2 * k + 3];
    if (tid < SD) {
        int i = tid;
        float acc = u[(size_t)(k + 1) * SD + i] + g_cP[i]
                  + g_ABw[i * 2] * wk0 + g_ABw[i * 2 + 1] * wk1
                  + Bw[i * 2] * wn0 + Bw[i * 2 + 1] * wn1;
        for (int j = 0; j < SD; j++) acc += g_At[j * SD + i] * us[j];
        g_P[(size_t)b * SD + i] = acc;
    } else if (tid >= 104 && tid < 112) {
        int z = tid - 104;
        float acc = g_cQ[z] + g_W1Bw[z * 2] * wk0 + g_W1Bw[z * 2 + 1] * wk1;
        for (int j = 0; j < SD; j++) acc += W1[z * SD + j] * us[j];
        g_Q[(size_t)b * HID + z] = acc;
    }
}

// ============================================================================
// 3) serial rollout over 32768 two-step blocks. 1 block, 128 threads.
//    s_k = [g_k (100) | h_k (8)].  Per block: one 108-dot per lane + tiny phase2.
//    Stores g_{k+2} into outc row (k+1) [raw g; fixed up by postEven],
//    h_{k+1}, h_{k+2} into g_h.
// ============================================================================
__global__ void __launch_bounds__(128, 1) serial_kernel(
    const float* __restrict__ c0,
    const float* __restrict__ W1,
    const float* __restrict__ b1,
    float* __restrict__ outc)
{
    __shared__ __align__(16) float sbuf[2][112];
    __shared__ __align__(16) float sh1[8];

    const int tid = threadIdx.x;
    const bool isG  = (tid < SD);
    const bool isM0 = (tid >= 104 && tid < 112);
    const bool isM1 = (tid >= 112 && tid < 120);
    const int z0 = tid - 104;
    const int z1 = tid - 112;

    if (tid < 112) { sbuf[0][tid] = (tid < SD) ? c0[tid] : 0.f; sbuf[1][tid] = 0.f; }

    unsigned long long rva[54];
#pragma unroll
    for (int q = 0; q < 54; q++) rva[q] = 0ull;
    unsigned long long w4[4] = {0ull, 0ull, 0ull, 0ull};
    float bias = 0.f;

    if (isG) {
        const float* R = g_A2 + tid * SD;
#pragma unroll
        for (int q = 0; q < 50; q++) rva[q] = pack2(R[2 * q], R[2 * q + 1]);
        const float* R2 = g_dtA2W2 + tid * HID;
#pragma unroll
        for (int q = 0; q < 4; q++) rva[50 + q] = pack2(R2[2 * q], R2[2 * q + 1]);
        const float* R3 = g_dtAW2 + tid * HID;
#pragma unroll
        for (int q = 0; q < 4; q++) w4[q] = pack2(R3[2 * q], R3[2 * q + 1]);
    } else if (isM0) {
        const float* R = W1 + z0 * SD;
#pragma unroll
        for (int q = 0; q < 50; q++) rva[q] = pack2(R[2 * q], R[2 * q + 1]);
        const float* R2 = g_dtW1W2 + z0 * HID;
#pragma unroll
        for (int q = 0; q < 4; q++) rva[50 + q] = pack2(R2[2 * q], R2[2 * q + 1]);
        bias = b1[z0];
    } else if (isM1) {
        const float* R = g_W1A + z1 * SD;
#pragma unroll
        for (int q = 0; q < 50; q++) rva[q] = pack2(R[2 * q], R[2 * q + 1]);
        const float* R2 = g_dtW1AW2 + z1 * HID;
#pragma unroll
        for (int q = 0; q < 4; q++) rva[50 + q] = pack2(R2[2 * q], R2[2 * q + 1]);
        const float* R3 = g_dtW1W2 + z1 * HID;
#pragma unroll
        for (int q = 0; q < 4; q++) w4[q] = pack2(R3[2 * q], R3[2 * q + 1]);
        bias = b1[z1];
    }
    __syncthreads();

    // prefetch P/Q, depth 2 blocks
    float p_c = 0.f, p_n = 0.f;
    if (isG)       { p_c = g_P[tid];       p_n = g_P[SD + tid]; }
    else if (isM1) { p_c = g_Q[z1];        p_n = g_Q[HID + z1]; }

    int p = 0;
    for (int b = 0; b < NB; b++) {
        const int bn = (b + 2 < NB) ? (b + 2) : (NB - 1);
        float p_n2 = 0.f;
        if (isG)       p_n2 = __ldcg(&g_P[(size_t)bn * SD + tid]);
        else if (isM1) p_n2 = __ldcg(&g_Q[(size_t)bn * HID + z1]);

        // ---- phase 1: one 108-dot against s_k (all lane classes concurrently)
        unsigned long long a0 = 0ull, a1 = 0ull, a2 = 0ull, a3 = 0ull;
        const ulonglong2* sp = reinterpret_cast<const ulonglong2*>(sbuf[p]);
#pragma unroll
        for (int q = 0; q < 27; q++) {
            ulonglong2 gg = sp[q];
            if (q & 1) { fma2(a2, rva[2 * q], gg.x); fma2(a3, rva[2 * q + 1], gg.y); }
            else       { fma2(a0, rva[2 * q], gg.x); fma2(a1, rva[2 * q + 1], gg.y); }
        }
        add2(a0, a1); add2(a2, a3); add2(a0, a2);
        float lo, hi; unpack2(a0, lo, hi);
        float dot = lo + hi;

        float h1r = 0.f;
        if (isM0) { h1r = tanh_hw(dot + bias); sh1[z0] = h1r; }
        __syncthreads();   // bar1: h_{k+1} visible

        // ---- phase 2: apply h_{k+1} coupling
        const ulonglong2* hp = reinterpret_cast<const ulonglong2*>(sh1);
        ulonglong2 Ha = hp[0], Hb = hp[1];
        if (isG) {
            unsigned long long c4 = 0ull;
            fma2(c4, w4[0], Ha.x); fma2(c4, w4[1], Ha.y);
            fma2(c4, w4[2], Hb.x); fma2(c4, w4[3], Hb.y);
            float l2, h2; unpack2(c4, l2, h2);
            float gn = dot + p_c + l2 + h2;
            sbuf[p ^ 1][tid] = gn;
            outc[(size_t)(2 * b + 1) * SD + tid] = gn;     // raw g_{k+2}
        } else if (isM1) {
            unsigned long long c4 = 0ull;
            fma2(c4, w4[0], Ha.x); fma2(c4, w4[1], Ha.y);
            fma2(c4, w4[2], Hb.x); fma2(c4, w4[3], Hb.y);
            float l2, h2; unpack2(c4, l2, h2);
            float hn = tanh_hw(dot + bias + p_c + l2 + h2);
            sbuf[p ^ 1][SD + z1] = hn;
            g_h[(size_t)(2 * b + 2) * HID + z1] = hn;
        } else if (isM0) {
            g_h[(size_t)(2 * b + 1) * HID + z0] = h1r;
        }

        p_c = p_n; p_n = p_n2;
        __syncthreads();   // bar2
        p ^= 1;
    }
}

// ============================================================================
// 4) postEven: even t (2..T): c_t = g_t + dt W2 h_t (in place, odd outc rows) + y
// ============================================================================
__global__ void postEven_kernel(const float* __restrict__ W2,
                                const int* __restrict__ obs,
                                float* __restrict__ outc,
                                float* __restrict__ outy)
{
    __shared__ float cs[SD];
    __shared__ float hh[HID];
    int t = 2 * blockIdx.x + 2;
    size_t r = (size_t)(t - 1);
    int tid = threadIdx.x;
    if (tid < HID) hh[tid] = g_h[(size_t)t * HID + tid];
    __syncthreads();
    if (tid < SD) {
        float g = outc[r * SD + tid];
        float s = 0.f;
#pragma unroll
        for (int z = 0; z < HID; z++) s += W2[tid * HID + z] * hh[z];
        float c = g + DTC * s;
        cs[tid] = c;
        outc[r * SD + tid] = c;
    }
    __syncthreads();
    if (tid < NOBS) outy[r * NOBS + tid] = cs[obs[tid]];
}

// ============================================================================
// 5) postOdd: odd t (1..T-1): c_t = A c_{t-1} + in_{t-1} + dt W2 h_t  + y
//    (c_{t-1} even: already finalized by postEven, or c0 for t=1)
// ============================================================================
__global__ void postOdd_kernel(const float* __restrict__ c0,
                               const float* __restrict__ w,
                               const float* __restrict__ u,
                               const float* __restrict__ Bw,
                               const float* __restrict__ W2,
                               const float* __restrict__ b2,
                               const int* __restrict__ obs,
                               float* __restrict__ outc,
                               float* __restrict__ outy)
{
    __shared__ float cp[SD];
    __shared__ float hh[HID];
    __shared__ float cs[SD];
    int b = blockIdx.x;
    int t = 2 * b + 1;
    size_t r = (size_t)(t - 1);
    int tid = threadIdx.x;
    if (tid < SD) cp[tid] = (b == 0) ? c0[tid] : outc[(r - 1) * SD + tid];
    if (tid < HID) hh[tid] = g_h[(size_t)t * HID + tid];
    __syncthreads();
    if (tid < SD) {
        int i = tid;
        float s = 0.f;
#pragma unroll
        for (int z = 0; z < HID; z++) s += W2[i * HID + z] * hh[z];
        float acc = u[(size_t)(t - 1) * SD + i] + DTC * (b2[i] + s)
                  + Bw[i * 2] * w[(t - 1) * 2] + Bw[i * 2 + 1] * w[(t - 1) * 2 + 1];
        for (int j = 0; j < SD; j++) acc += g_At[j * SD + i] * cp[j];
        cs[i] = acc;
        outc[r * SD + i] = acc;
    }
    __syncthreads();
    if (tid < NOBS) outy[r * NOBS + tid] = cs[obs[tid]];
}

extern "C" void kernel_launch(void* const* d_in, const int* in_sizes, int n_in,
                              void* d_out, int out_size) {
    const float* c0  = (const float*)d_in[0];
    const float* w   = (const float*)d_in[1];
    const float* u   = (const float*)d_in[2];
    const float* A   = (const float*)d_in[3];
    const float* Bw  = (const float*)d_in[4];
    const float* W1  = (const float*)d_in[5];
    const float* b1  = (const float*)d_in[6];
    const float* W2  = (const float*)d_in[7];
    const float* b2  = (const float*)d_in[8];
    const int*   ob  = (const int*)d_in[9];

    float* outc = (float*)d_out;                      // (T, 100)
    float* outy = (float*)d_out + (size_t)TT * SD;    // (T, 12)

    setup_kernel<<<1, 128>>>(A, Bw, W1, W2, b2);
    precomp_kernel<<<NB, 128>>>(w, u, Bw, W1);
    serial_kernel<<<1, 128>>>(c0, W1, b1, outc);
    postEven_kernel<<<NB, 128>>>(W2, ob, outc, outy);
    postOdd_kernel<<<NB, 128>>>(c0, w, u, Bw, W2, b2, ob, outc, outy);
}